// round 9
// baseline (speedup 1.0000x reference)
#include <cuda_runtime.h>
#include <math.h>
#include <stdint.h>

#define NN 50000
#define NE 800000
#define D  128
#define DE 16
#define G4 512   // 4*D gates

// ---------------- scratch (static device globals; no allocation) ----------------
__device__ __align__(16) float g_W[2 * D * D];        // evolving LSTM state (hs) per layer
__device__ __align__(16) float g_G0[2 * D * G4];      // precomputed Wih@x + b per layer
__device__ __align__(16) float g_WihT[2 * D * G4];    // transposed Wih for coalesced G0 GEMM
__device__ __align__(16) float g_ft[(size_t)NN * D];  // nf @ W
__device__ __align__(16) float g_feat[(size_t)NN * D];// layer-0 GAT output (post leaky)
__device__ float  g_sc2[NE];      // edge score in dst-sorted order
__device__ float2 g_edot2[NE];    // (layer0, layer1) ef @ a_edge, dst-sorted order
__device__ float  g_ssrc[NN];
__device__ float  g_sdst[NN];
// ---- dst-sorted edge structure (built once; graph identical across layers) ----
__device__ int g_cnt[NN + 1];     // counts -> exclusive offsets (in place)
__device__ int g_cur[NN];         // scatter cursors
__device__ int g_ssorted[NE];     // sorted position -> src node

// packed f32x2 FMA (sm_103a FFMA2) — PTX-only, ptxas won't auto-fuse
__device__ __forceinline__ unsigned long long fma2(
    unsigned long long a, unsigned long long b, unsigned long long c)
{
    unsigned long long d;
    asm("fma.rn.f32x2 %0, %1, %2, %3;" : "=l"(d) : "l"(a), "l"(b), "l"(c));
    return d;
}
__device__ __forceinline__ unsigned long long dup2(float x) {
    unsigned long long r;
    asm("mov.b64 %0, {%1,%1};" : "=l"(r) : "r"(__float_as_uint(x)));
    return r;
}
__device__ __forceinline__ float hsum2(unsigned long long a) {
    return __uint_as_float((unsigned)a) + __uint_as_float((unsigned)(a >> 32));
}
__device__ __forceinline__ float lo2(unsigned long long a) { return __uint_as_float((unsigned)a); }
__device__ __forceinline__ float hi2(unsigned long long a) { return __uint_as_float((unsigned)(a >> 32)); }
__device__ __forceinline__ float tanh_fast(float x) {
    float r; asm("tanh.approx.f32 %0, %1;" : "=f"(r) : "f"(x)); return r;
}
__device__ __forceinline__ float sig_fast(float x) {
    return __fdividef(1.f, 1.f + __expf(-x));
}

// ---------------- edge sort (once) ----------------

__global__ void k_zero_cnt() {
    int idx = blockIdx.x * 256 + threadIdx.x;
    if (idx <= NN) g_cnt[idx] = 0;
}

__global__ void k_hist(const int* __restrict__ dst) {
    int e = blockIdx.x * 256 + threadIdx.x;
    if (e < NE) atomicAdd(&g_cnt[dst[e]], 1);
}

// single-CTA exclusive scan over 50k counts; writes offsets into g_cnt and g_cur
__global__ void __launch_bounds__(1024) k_scan() {
    const int CH = 49;                     // 1024*49 = 50176 >= NN
    int tid = threadIdx.x;
    int lane = tid & 31, wid = tid >> 5;
    int base = tid * CH;
    int s = 0;
    for (int i = 0; i < CH; i++) {
        int j = base + i;
        if (j < NN) s += g_cnt[j];
    }
    __shared__ int wsum[32];
    int v = s;
#pragma unroll
    for (int o = 1; o < 32; o <<= 1) {
        int t = __shfl_up_sync(0xffffffffu, v, o);
        if (lane >= o) v += t;
    }
    if (lane == 31) wsum[wid] = v;
    __syncthreads();
    if (wid == 0) {
        int w = wsum[lane];
#pragma unroll
        for (int o = 1; o < 32; o <<= 1) {
            int t = __shfl_up_sync(0xffffffffu, w, o);
            if (lane >= o) w += t;
        }
        wsum[lane] = w;
    }
    __syncthreads();
    int run = v - s + (wid ? wsum[wid - 1] : 0);   // exclusive prefix
    for (int i = 0; i < CH; i++) {
        int j = base + i;
        if (j < NN) {
            int c = g_cnt[j];
            g_cnt[j] = run;
            g_cur[j] = run;
            run += c;
        }
    }
    if (tid == 1023) g_cnt[NN] = NE;
}

// scatter + fused edge-feature dot for BOTH layers (ef read once, ever);
// edot stored interleaved float2 -> one random 8B store per edge
__global__ void __launch_bounds__(256) k_scatter(
    const int* __restrict__ src, const int* __restrict__ dst,
    const float* __restrict__ ef, const float* __restrict__ a_w)
{
    int e = blockIdx.x * 256 + threadIdx.x;
    if (e >= NE) return;
    int d = dst[e];
    int pos = atomicAdd(&g_cur[d], 1);
    g_ssorted[pos] = src[e];
    const float4* ep = (const float4*)(ef + (size_t)e * DE);
    const float* ae0 = a_w + D;
    const float* ae1 = a_w + (2 * D + DE) + D;
    float d0 = 0.f, d1 = 0.f;
#pragma unroll
    for (int i = 0; i < 4; i++) {
        float4 v = ep[i];
        d0 += v.x * __ldg(ae0 + i * 4)     + v.y * __ldg(ae0 + i * 4 + 1)
            + v.z * __ldg(ae0 + i * 4 + 2) + v.w * __ldg(ae0 + i * 4 + 3);
        d1 += v.x * __ldg(ae1 + i * 4)     + v.y * __ldg(ae1 + i * 4 + 1)
            + v.z * __ldg(ae1 + i * 4 + 2) + v.w * __ldg(ae1 + i * 4 + 3);
    }
    g_edot2[pos] = make_float2(d0, d1);
}

// ---------------- LSTM ----------------

// transpose Wih (L,512,128) -> WihT (L,128,512) for coalesced reads in G0
__global__ void k_transpose_wih(const float* __restrict__ Wih) {
    int idx = blockIdx.x * 256 + threadIdx.x;
    if (idx >= 2 * G4 * D) return;
    int layer = idx / (G4 * D);
    int rem   = idx - layer * (G4 * D);
    int g = rem / D, k = rem % D;
    g_WihT[(size_t)layer * (D * G4) + k * G4 + g] = Wih[idx];
}

// G0[t][g] = b[g] + sum_k X[t][k] * Wih[g][k]; 4 t-rows per block (WihT reuse 4x)
__global__ void __launch_bounds__(512) k_lstm_g0(
    const float* __restrict__ Xext, int use_state,
    const float* __restrict__ bih, const float* __restrict__ bhh)
{
    int layer = blockIdx.y;
    int t0 = blockIdx.x * 4;
    int g = threadIdx.x;
    __shared__ float xs[4 * D];
    const float* X = use_state ? (g_W + layer * D * D) : (Xext + layer * D * D);
    xs[g] = X[t0 * D + g];   // 512 threads cover rows t0..t0+3 contiguously
    __syncthreads();
    const float* wt = g_WihT + (size_t)layer * (D * G4) + g;
    float b = bih[layer * G4 + g] + bhh[layer * G4 + g];
    float a0 = 0.f, a1 = 0.f, a2 = 0.f, a3 = 0.f;
#pragma unroll 4
    for (int k = 0; k < D; k++) {
        float w = wt[k * G4];
        a0 = fmaf(w, xs[k],         a0);
        a1 = fmaf(w, xs[D + k],     a1);
        a2 = fmaf(w, xs[2 * D + k], a2);
        a3 = fmaf(w, xs[3 * D + k], a3);
    }
    size_t o = (size_t)(layer * D + t0) * G4 + g;
    g_G0[o]          = a0 + b;
    g_G0[o + G4]     = a1 + b;
    g_G0[o + 2 * G4] = a2 + b;
    g_G0[o + 3 * G4] = a3 + b;
}

// 128-step recurrence, one CTA of 1024 threads per layer (grid=2).
// thread = (half = tid>>9, row r = tid&511), k in [half*64, half*64+64):
//   k 0..39 in regs (20 u64), k 40..63 in smem. 2 barriers per step:
//   all threads write partial[tid]; threads tid<128 combine all 8 partials
//   (4 gate rows x 2 halves), do activations + c/h update in one stage.
__global__ void __launch_bounds__(1024, 1) k_lstm_rec(const float* __restrict__ Whh)
{
    int layer = blockIdx.x;
    extern __shared__ float sh[];
    float4* wsm  = (float4*)sh;              // [6][1024] float4 = 96KB
    float*  hsm  = sh + 6 * 1024 * 4;        // 128 floats
    float*  part = hsm + 128;                // 1024 floats

    int tid  = threadIdx.x;
    int half = tid >> 9;
    int r    = tid & 511;

    const float* wrow = Whh + ((size_t)(layer * G4 + r)) * D + half * 64;
    unsigned long long wreg[20];
#pragma unroll
    for (int j = 0; j < 20; j++)
        wreg[j] = *(const unsigned long long*)(wrow + 2 * j);
#pragma unroll
    for (int j = 0; j < 6; j++)
        wsm[j * 1024 + tid] = *(const float4*)(wrow + 40 + 4 * j);

    if (tid < D) hsm[tid] = 0.f;
    float c = 0.f;
    const float* g0 = g_G0 + (size_t)layer * (D * G4);
    float* ws = g_W + layer * D * D;
    __syncthreads();

    const ulonglong2* h2 = (const ulonglong2*)(hsm + half * 64);
    const ulonglong2* wt = (const ulonglong2*)wsm + tid;

    for (int t = 0; t < D; t++) {
        // prefetch g0 for the epilogue threads (hidden under the FMA phase)
        float q0, q1, q2, q3;
        if (tid < D) {
            const float* gp = g0 + t * G4 + tid;
            q0 = __ldg(gp);       q1 = __ldg(gp + 128);
            q2 = __ldg(gp + 256); q3 = __ldg(gp + 384);
        }

        unsigned long long a0 = 0ull, a1 = 0ull;
#pragma unroll
        for (int j = 0; j < 10; j++) {
            ulonglong2 hh = h2[j];
            a0 = fma2(wreg[2 * j],     hh.x, a0);
            a1 = fma2(wreg[2 * j + 1], hh.y, a1);
        }
#pragma unroll
        for (int j = 0; j < 6; j++) {
            ulonglong2 w  = wt[j * 1024];
            ulonglong2 hh = h2[10 + j];
            a0 = fma2(w.x, hh.x, a0);
            a1 = fma2(w.y, hh.y, a1);
        }
        part[tid] = hsum2(a0) + hsum2(a1);
        __syncthreads();

        if (tid < D) {
            float gi = q0 + part[tid]       + part[tid + 512];
            float gf = q1 + part[tid + 128] + part[tid + 640];
            float gg = q2 + part[tid + 256] + part[tid + 768];
            float go = q3 + part[tid + 384] + part[tid + 896];
            float iv = sig_fast(gi), fv = sig_fast(gf);
            float gv = tanh_fast(gg), ov = sig_fast(go);
            c = fmaf(fv, c, iv * gv);
            float h = ov * tanh_fast(c);
            hsm[tid] = h;
            ws[t * D + tid] = h;
        }
        __syncthreads();
    }
}

// ---------------- GAT ----------------

// Register-tiled GEMM: CTA = 64 rows x 128 cols, thread = 8 rows x 4 cols.
__global__ void __launch_bounds__(256, 2) k_gat_gemm(
    const float* __restrict__ nf_ext, int layer, const float* __restrict__ a_w)
{
    extern __shared__ float sh[];
    float* Wsm = sh;               // 16384 floats (64KB)
    float* Xs  = sh + D * D;       // 64*128 floats (32KB)
    float* av  = Xs + 64 * D;      // a_src[128], a_dst[128]
    int tid = threadIdx.x;

    const float4* Wg4 = (const float4*)(g_W + layer * D * D);
    float4* Wsm4 = (float4*)Wsm;
    for (int i = tid; i < D * D / 4; i += 256) Wsm4[i] = Wg4[i];

    const float* aw = a_w + layer * (2 * D + DE);
    if (tid < D) { av[tid] = aw[tid]; av[D + tid] = aw[D + DE + tid]; }

    const float* nf = layer ? g_feat : nf_ext;
    int row0 = blockIdx.x * 64;
    float4* Xs4 = (float4*)Xs;
    for (int i = tid; i < 64 * 32; i += 256) {
        int r = i >> 5, cc = i & 31;
        int gr = row0 + r;
        float4 v = make_float4(0.f, 0.f, 0.f, 0.f);
        if (gr < NN) v = ((const float4*)(nf + (size_t)gr * D))[cc];
        Xs4[i] = v;
    }
    __syncthreads();

    int lane = tid & 31, wid = tid >> 5;

    const float4* as4 = (const float4*)av;
    const float4* ad4 = (const float4*)(av + D);
#pragma unroll
    for (int i = 0; i < 8; i++) {
        int lr = wid * 8 + i;
        float4 x = Xs4[lr * 32 + lane];
        float4 a = as4[lane], b = ad4[lane];
        float ss = x.x * a.x + x.y * a.y + x.z * a.z + x.w * a.w;
        float sd = x.x * b.x + x.y * b.y + x.z * b.z + x.w * b.w;
#pragma unroll
        for (int o = 16; o; o >>= 1) {
            ss += __shfl_xor_sync(0xffffffffu, ss, o);
            sd += __shfl_xor_sync(0xffffffffu, sd, o);
        }
        int gr = row0 + lr;
        if (lane == 0 && gr < NN) { g_ssrc[gr] = ss; g_sdst[gr] = sd; }
    }

    const ulonglong2* W2 = (const ulonglong2*)Wsm;
    unsigned long long acc[8][2];
#pragma unroll
    for (int i = 0; i < 8; i++) { acc[i][0] = 0ull; acc[i][1] = 0ull; }

#pragma unroll 8
    for (int k4 = 0; k4 < 32; k4++) {
        ulonglong2 w0 = W2[(k4 * 4 + 0) * 32 + lane];
        ulonglong2 w1 = W2[(k4 * 4 + 1) * 32 + lane];
        ulonglong2 w2 = W2[(k4 * 4 + 2) * 32 + lane];
        ulonglong2 w3 = W2[(k4 * 4 + 3) * 32 + lane];
#pragma unroll
        for (int i = 0; i < 8; i++) {
            float4 xv = Xs4[(wid * 8 + i) * 32 + k4];
            unsigned long long xx;
            xx = dup2(xv.x);
            acc[i][0] = fma2(w0.x, xx, acc[i][0]); acc[i][1] = fma2(w0.y, xx, acc[i][1]);
            xx = dup2(xv.y);
            acc[i][0] = fma2(w1.x, xx, acc[i][0]); acc[i][1] = fma2(w1.y, xx, acc[i][1]);
            xx = dup2(xv.z);
            acc[i][0] = fma2(w2.x, xx, acc[i][0]); acc[i][1] = fma2(w2.y, xx, acc[i][1]);
            xx = dup2(xv.w);
            acc[i][0] = fma2(w3.x, xx, acc[i][0]); acc[i][1] = fma2(w3.y, xx, acc[i][1]);
        }
    }

#pragma unroll
    for (int i = 0; i < 8; i++) {
        int gr = row0 + wid * 8 + i;
        if (gr < NN) {
            float4 o;
            o.x = lo2(acc[i][0]); o.y = hi2(acc[i][0]);
            o.z = lo2(acc[i][1]); o.w = hi2(acc[i][1]);
            ((float4*)(g_ft + (size_t)gr * D))[lane] = o;
        }
    }
}

// fused per-node score + online softmax + aggregation: warp per dst node.
// dest + edot resolved IN DEVICE CODE (host-side &g_feat is garbage).
__global__ void __launch_bounds__(256) k_node_fused(
    float* __restrict__ dest_ext, int to_internal, int layer)
{
    int n = (blockIdx.x * 256 + threadIdx.x) >> 5;
    int lane = threadIdx.x & 31;
    if (n >= NN) return;
    float* dest = to_internal ? g_feat : dest_ext;
    int off = g_cnt[n], end = g_cnt[n + 1];
    float sdn = g_sdst[n];

    // pass 1: score + online max/denominator
    float m = -1e30f, den = 0.f;
    for (int j = off + lane; j < end; j += 32) {
        int s = g_ssorted[j];
        float2 ed = g_edot2[j];
        float sc = g_ssrc[s] + sdn + (layer ? ed.y : ed.x);
        g_sc2[j] = sc;
        if (sc > m) { den = den * __expf(m - sc) + 1.f; m = sc; }
        else den += __expf(sc - m);
    }
#pragma unroll
    for (int o = 16; o; o >>= 1) {
        float mo = __shfl_xor_sync(0xffffffffu, m, o);
        float dn = __shfl_xor_sync(0xffffffffu, den, o);
        float mn = fmaxf(m, mo);
        den = den * __expf(m - mn) + dn * __expf(mo - mn);
        m = mn;
    }
    float inv_den = den > 0.f ? __fdividef(1.f, den) : 0.f;

    // pass 2: aggregate (2-deep pipelined gather, packed fma2)
    unsigned long long acc0 = 0ull, acc1 = 0ull;
    for (int jb = off; jb < end; jb += 32) {
        int j = jb + lane;
        float al = 0.f; int sv = 0;
        if (j < end) {
            sv = g_ssorted[j];
            al = __expf(g_sc2[j] - m) * inv_den;
        }
        int cnt = min(32, end - jb);
        int k = 0;
        for (; k + 2 <= cnt; k += 2) {
            float a0f = __shfl_sync(0xffffffffu, al, k);
            float a1f = __shfl_sync(0xffffffffu, al, k + 1);
            int s0 = __shfl_sync(0xffffffffu, sv, k);
            int s1 = __shfl_sync(0xffffffffu, sv, k + 1);
            ulonglong2 v0 = ((const ulonglong2*)(g_ft + (size_t)s0 * D))[lane];
            ulonglong2 v1 = ((const ulonglong2*)(g_ft + (size_t)s1 * D))[lane];
            unsigned long long aa0 = dup2(a0f), aa1 = dup2(a1f);
            acc0 = fma2(v0.x, aa0, acc0); acc1 = fma2(v0.y, aa0, acc1);
            acc0 = fma2(v1.x, aa1, acc0); acc1 = fma2(v1.y, aa1, acc1);
        }
        if (k < cnt) {
            float a0f = __shfl_sync(0xffffffffu, al, k);
            int s0 = __shfl_sync(0xffffffffu, sv, k);
            ulonglong2 v0 = ((const ulonglong2*)(g_ft + (size_t)s0 * D))[lane];
            unsigned long long aa0 = dup2(a0f);
            acc0 = fma2(v0.x, aa0, acc0); acc1 = fma2(v0.y, aa0, acc1);
        }
    }
    float4 o;
    o.x = lo2(acc0); o.y = hi2(acc0); o.z = lo2(acc1); o.w = hi2(acc1);
    o.x = o.x >= 0.f ? o.x : 0.01f * o.x;
    o.y = o.y >= 0.f ? o.y : 0.01f * o.y;
    o.z = o.z >= 0.f ? o.z : 0.01f * o.z;
    o.w = o.w >= 0.f ? o.w : 0.01f * o.w;
    ((float4*)(dest + (size_t)n * D))[lane] = o;
}

// ---------------- launch ----------------
extern "C" void kernel_launch(void* const* d_in, const int* in_sizes, int n_in,
                              void* d_out, int out_size)
{
    const int*   src     = (const int*)  d_in[0];
    const int*   dst     = (const int*)  d_in[1];
    const float* n_feats = (const float*)d_in[2];
    const float* e_feats = (const float*)d_in[3];
    const float* W0      = (const float*)d_in[4];
    const float* Wih     = (const float*)d_in[5];
    const float* Whh     = (const float*)d_in[6];
    const float* bih     = (const float*)d_in[7];
    const float* bhh     = (const float*)d_in[8];
    const float* a_w     = (const float*)d_in[9];

    int n_edges = in_sizes[0] / 3;        // 800000
    int n_nodes = in_sizes[2] / (3 * D);  // 50000

    int smem_rec  = 6 * 1024 * 16 + (128 + 1024) * (int)sizeof(float);  // ~100.5KB
    int smem_gemm = (D * D + 64 * D + 2 * D) * (int)sizeof(float);      // ~97KB
    cudaFuncSetAttribute(k_lstm_rec, cudaFuncAttributeMaxDynamicSharedMemorySize, smem_rec);
    cudaFuncSetAttribute(k_gat_gemm, cudaFuncAttributeMaxDynamicSharedMemorySize, smem_gemm);

    // only timestep j=2 matters for the output (feats never mix across j)
    const int*   src2 = src + 2 * n_edges;
    const int*   dst2 = dst + 2 * n_edges;
    const float* nf2  = n_feats + (size_t)2 * n_nodes * D;
    const float* ef2  = e_feats + (size_t)2 * n_edges * DE;

    // launch order chosen so ncu (-s 5 -c 1) profiles k_lstm_rec (index 5)
    k_zero_cnt<<<(NN + 256) / 256, 256>>>();                         // 0
    k_transpose_wih<<<(2 * G4 * D + 255) / 256, 256>>>(Wih);         // 1
    for (int call = 0; call < 3; call++) {
        k_lstm_g0<<<dim3(D / 4, 2), 512>>>(W0, call > 0, bih, bhh);  // 2,4,6
        k_lstm_rec<<<2, 1024, smem_rec>>>(Whh);                      // 3,5,7
    }

    // dst-sorted edge structure + both layers' edge dots (needed only by fused)
    k_hist<<<(n_edges + 255) / 256, 256>>>(dst2);                    // 8
    k_scan<<<1, 1024>>>();                                           // 9
    k_scatter<<<(n_edges + 255) / 256, 256>>>(src2, dst2, ef2, a_w); // 10

    for (int layer = 0; layer < 2; layer++) {
        k_gat_gemm<<<(n_nodes + 63) / 64, 256, smem_gemm>>>(nf2, layer, a_w);
        k_node_fused<<<(n_nodes * 32 + 255) / 256, 256>>>((float*)d_out, layer == 0 ? 1 : 0, layer);
    }
}

// round 10
// speedup vs baseline: 1.4766x; 1.4766x over previous
#include <cuda_runtime.h>
#include <math.h>
#include <stdint.h>

#define NN 50000
#define NE 800000
#define D  128
#define DE 16
#define G4 512   // 4*D gates

// ---------------- scratch (static device globals; no allocation) ----------------
__device__ __align__(16) float g_W[2 * D * D];        // evolving LSTM state (hs) per layer
__device__ __align__(16) float g_G0[2 * D * G4];      // precomputed Wih@x + b per layer
__device__ __align__(16) float g_WihT[2 * D * G4];    // transposed Wih for coalesced G0 GEMM
__device__ __align__(16) float g_ft[(size_t)NN * D];  // nf @ W
__device__ __align__(16) float g_feat[(size_t)NN * D];// layer-0 GAT output (post leaky)
__device__ float  g_sc2[NE];      // edge score in dst-sorted order
__device__ float2 g_edot2[NE];    // (layer0, layer1) ef @ a_edge, dst-sorted order
__device__ float  g_ssrc[NN];
__device__ float  g_sdst[NN];
// ---- dst-sorted edge structure (built once; graph identical across layers) ----
__device__ int g_cnt[NN + 1];     // counts -> exclusive offsets (in place)
__device__ int g_cur[NN];         // scatter cursors
__device__ int g_ssorted[NE];     // sorted position -> src node

// packed f32x2 FMA (sm_103a FFMA2) — PTX-only, ptxas won't auto-fuse
__device__ __forceinline__ unsigned long long fma2(
    unsigned long long a, unsigned long long b, unsigned long long c)
{
    unsigned long long d;
    asm("fma.rn.f32x2 %0, %1, %2, %3;" : "=l"(d) : "l"(a), "l"(b), "l"(c));
    return d;
}
__device__ __forceinline__ unsigned long long dup2(float x) {
    unsigned long long r;
    asm("mov.b64 %0, {%1,%1};" : "=l"(r) : "r"(__float_as_uint(x)));
    return r;
}
__device__ __forceinline__ float hsum2(unsigned long long a) {
    return __uint_as_float((unsigned)a) + __uint_as_float((unsigned)(a >> 32));
}
__device__ __forceinline__ float lo2(unsigned long long a) { return __uint_as_float((unsigned)a); }
__device__ __forceinline__ float hi2(unsigned long long a) { return __uint_as_float((unsigned)(a >> 32)); }
__device__ __forceinline__ float tanh_fast(float x) {
    float r; asm("tanh.approx.f32 %0, %1;" : "=f"(r) : "f"(x)); return r;
}
__device__ __forceinline__ float sig_fast(float x) {
    return __fdividef(1.f, 1.f + __expf(-x));
}
__device__ __forceinline__ uint32_t smem_u32(const void* p) {
    uint32_t a;
    asm("{ .reg .u64 t; cvta.to.shared.u64 t, %1; cvt.u32.u64 %0, t; }" : "=r"(a) : "l"(p));
    return a;
}
__device__ __forceinline__ void mbar_wait_cluster(uint32_t mbar, uint32_t parity) {
    asm volatile(
        "{\n\t.reg .pred P1;\n\t"
        "WAIT_LOOP_%=:\n\t"
        "mbarrier.try_wait.parity.acquire.cluster.shared::cta.b64 P1, [%0], %1, 0x989680;\n\t"
        "@P1 bra.uni WAIT_DONE_%=;\n\t"
        "bra.uni WAIT_LOOP_%=;\n\t"
        "WAIT_DONE_%=:\n\t}"
        :: "r"(mbar), "r"(parity) : "memory");
}

// ---------------- edge sort (once) ----------------

__global__ void k_zero_cnt() {
    int idx = blockIdx.x * 256 + threadIdx.x;
    if (idx <= NN) g_cnt[idx] = 0;
}

__global__ void k_hist(const int* __restrict__ dst) {
    int e = blockIdx.x * 256 + threadIdx.x;
    if (e < NE) atomicAdd(&g_cnt[dst[e]], 1);
}

// single-CTA exclusive scan over 50k counts; writes offsets into g_cnt and g_cur
__global__ void __launch_bounds__(1024) k_scan() {
    const int CH = 49;                     // 1024*49 = 50176 >= NN
    int tid = threadIdx.x;
    int lane = tid & 31, wid = tid >> 5;
    int base = tid * CH;
    int s = 0;
    for (int i = 0; i < CH; i++) {
        int j = base + i;
        if (j < NN) s += g_cnt[j];
    }
    __shared__ int wsum[32];
    int v = s;
#pragma unroll
    for (int o = 1; o < 32; o <<= 1) {
        int t = __shfl_up_sync(0xffffffffu, v, o);
        if (lane >= o) v += t;
    }
    if (lane == 31) wsum[wid] = v;
    __syncthreads();
    if (wid == 0) {
        int w = wsum[lane];
#pragma unroll
        for (int o = 1; o < 32; o <<= 1) {
            int t = __shfl_up_sync(0xffffffffu, w, o);
            if (lane >= o) w += t;
        }
        wsum[lane] = w;
    }
    __syncthreads();
    int run = v - s + (wid ? wsum[wid - 1] : 0);   // exclusive prefix
    for (int i = 0; i < CH; i++) {
        int j = base + i;
        if (j < NN) {
            int c = g_cnt[j];
            g_cnt[j] = run;
            g_cur[j] = run;
            run += c;
        }
    }
    if (tid == 1023) g_cnt[NN] = NE;
}

// scatter + fused edge-feature dot for BOTH layers (ef read once, ever)
__global__ void __launch_bounds__(256) k_scatter(
    const int* __restrict__ src, const int* __restrict__ dst,
    const float* __restrict__ ef, const float* __restrict__ a_w)
{
    int e = blockIdx.x * 256 + threadIdx.x;
    if (e >= NE) return;
    int d = dst[e];
    int pos = atomicAdd(&g_cur[d], 1);
    g_ssorted[pos] = src[e];
    const float4* ep = (const float4*)(ef + (size_t)e * DE);
    const float* ae0 = a_w + D;
    const float* ae1 = a_w + (2 * D + DE) + D;
    float d0 = 0.f, d1 = 0.f;
#pragma unroll
    for (int i = 0; i < 4; i++) {
        float4 v = ep[i];
        d0 += v.x * __ldg(ae0 + i * 4)     + v.y * __ldg(ae0 + i * 4 + 1)
            + v.z * __ldg(ae0 + i * 4 + 2) + v.w * __ldg(ae0 + i * 4 + 3);
        d1 += v.x * __ldg(ae1 + i * 4)     + v.y * __ldg(ae1 + i * 4 + 1)
            + v.z * __ldg(ae1 + i * 4 + 2) + v.w * __ldg(ae1 + i * 4 + 3);
    }
    g_edot2[pos] = make_float2(d0, d1);
}

// ---------------- LSTM ----------------

// transpose Wih (L,512,128) -> WihT (L,128,512) for coalesced reads in G0
__global__ void k_transpose_wih(const float* __restrict__ Wih) {
    int idx = blockIdx.x * 256 + threadIdx.x;
    if (idx >= 2 * G4 * D) return;
    int layer = idx / (G4 * D);
    int rem   = idx - layer * (G4 * D);
    int g = rem / D, k = rem % D;
    g_WihT[(size_t)layer * (D * G4) + k * G4 + g] = Wih[idx];
}

// G0[t][g] = b[g] + sum_k X[t][k] * Wih[g][k]; 4 t-rows per block (WihT reuse 4x)
__global__ void __launch_bounds__(512) k_lstm_g0(
    const float* __restrict__ Xext, int use_state,
    const float* __restrict__ bih, const float* __restrict__ bhh)
{
    int layer = blockIdx.y;
    int t0 = blockIdx.x * 4;
    int g = threadIdx.x;
    __shared__ float xs[4 * D];
    const float* X = use_state ? (g_W + layer * D * D) : (Xext + layer * D * D);
    xs[g] = X[t0 * D + g];
    __syncthreads();
    const float* wt = g_WihT + (size_t)layer * (D * G4) + g;
    float b = bih[layer * G4 + g] + bhh[layer * G4 + g];
    float a0 = 0.f, a1 = 0.f, a2 = 0.f, a3 = 0.f;
#pragma unroll 4
    for (int k = 0; k < D; k++) {
        float w = wt[k * G4];
        a0 = fmaf(w, xs[k],         a0);
        a1 = fmaf(w, xs[D + k],     a1);
        a2 = fmaf(w, xs[2 * D + k], a2);
        a3 = fmaf(w, xs[3 * D + k], a3);
    }
    size_t o = (size_t)(layer * D + t0) * G4 + g;
    g_G0[o]          = a0 + b;
    g_G0[o + G4]     = a1 + b;
    g_G0[o + 2 * G4] = a2 + b;
    g_G0[o + 3 * G4] = a3 + b;
}

// 128-step recurrence, 2-CTA cluster per layer (grid=4, cluster=2).
// CTA rank R covers k in [R*64, R*64+64); thread = (half=tid>>9, row r=tid&511)
// holds W[r, R*64+half*32 .. +32) entirely in 16 u64 registers (ZERO smem W).
// Per step: FMA -> exchange 4KB raw partials with peer via st.async+mbarrier
// (double-buffered by step parity) -> replicated epilogue in both CTAs.
__global__ void __launch_bounds__(1024, 1) __cluster_dims__(2, 1, 1)
k_lstm_rec(const float* __restrict__ Whh)
{
    __shared__ __align__(16) float hsm[D];
    __shared__ __align__(16) float praw_loc[1024];
    __shared__ __align__(16) float praw_rem[2][1024];   // double buffer (step parity)
    __shared__ __align__(8)  unsigned long long mbar_s;

    int tid = threadIdx.x;
    int layer = blockIdx.x >> 1;
    uint32_t rank;
    asm("mov.u32 %0, %%cluster_ctarank;" : "=r"(rank));
    uint32_t peer = rank ^ 1u;

    int half = tid >> 9;
    int r    = tid & 511;

    // this thread's 32 W floats -> 16 u64 registers
    const float* wrow = Whh + ((size_t)(layer * G4 + r)) * D + rank * 64 + half * 32;
    unsigned long long wreg[16];
#pragma unroll
    for (int j = 0; j < 16; j++)
        wreg[j] = *(const unsigned long long*)(wrow + 2 * j);

    uint32_t mbar_addr = smem_u32(&mbar_s);
    uint32_t rem_base  = smem_u32(&praw_rem[0][0]);
    uint32_t remote_base, remote_mbar;
    asm("mapa.shared::cluster.u32 %0, %1, %2;" : "=r"(remote_base) : "r"(rem_base), "r"(peer));
    asm("mapa.shared::cluster.u32 %0, %1, %2;" : "=r"(remote_mbar) : "r"(mbar_addr), "r"(peer));

    if (tid == 0)
        asm volatile("mbarrier.init.shared.b64 [%0], 1;" :: "r"(mbar_addr) : "memory");
    if (tid < D) hsm[tid] = 0.f;
    float c = 0.f;
    const float* g0 = g_G0 + (size_t)layer * (D * G4);
    float* ws = g_W + layer * D * D;
    __syncthreads();
    // mbarriers + hsm init must be cluster-visible before any peer st.async
    asm volatile("barrier.cluster.arrive.aligned;" ::: "memory");
    asm volatile("barrier.cluster.wait.aligned;"   ::: "memory");

    const ulonglong2* h2 = (const ulonglong2*)(hsm + rank * 64 + half * 32);
    uint32_t remote_dst0 = remote_base + tid * 4;           // buffer 0 slot
    const float* gp = g0 + tid;                             // epilogue g0 stream

    for (int t = 0; t < D; t++) {
        if (tid == 0)
            asm volatile("mbarrier.arrive.expect_tx.shared::cta.b64 _, [%0], 4096;"
                         :: "r"(mbar_addr) : "memory");
        // prefetch epilogue inputs (hidden under FMA)
        float q0, q1, q2, q3;
        if (tid < D) {
            q0 = __ldg(gp);       q1 = __ldg(gp + 128);
            q2 = __ldg(gp + 256); q3 = __ldg(gp + 384);
        }

        unsigned long long a0 = 0ull, a1 = 0ull;
#pragma unroll
        for (int j = 0; j < 8; j++) {
            ulonglong2 hh = h2[j];                          // warp-broadcast LDS
            a0 = fma2(wreg[2 * j],     hh.x, a0);
            a1 = fma2(wreg[2 * j + 1], hh.y, a1);
        }
        float own = hsum2(a0) + hsum2(a1);
        praw_loc[tid] = own;
        asm volatile("st.async.shared::cluster.mbarrier::complete_tx::bytes.b32 [%0], %1, [%2];"
                     :: "r"(remote_dst0 + (t & 1) * 4096), "r"(__float_as_uint(own)),
                        "r"(remote_mbar) : "memory");
        __syncthreads();                                    // praw_loc visible

        if (tid < D) {
            mbar_wait_cluster(mbar_addr, t & 1);            // peer's 4KB landed
            const float* pr = praw_rem[t & 1];
            float gi = q0 + praw_loc[tid]       + praw_loc[tid + 512]
                          + pr[tid]             + pr[tid + 512];
            float gf = q1 + praw_loc[tid + 128] + praw_loc[tid + 640]
                          + pr[tid + 128]       + pr[tid + 640];
            float gg = q2 + praw_loc[tid + 256] + praw_loc[tid + 768]
                          + pr[tid + 256]       + pr[tid + 768];
            float go = q3 + praw_loc[tid + 384] + praw_loc[tid + 896]
                          + pr[tid + 384]       + pr[tid + 896];
            float iv = sig_fast(gi), fv = sig_fast(gf);
            float gv = tanh_fast(gg), ov = sig_fast(go);
            c = fmaf(fv, c, iv * gv);
            float h = ov * tanh_fast(c);
            hsm[tid] = h;
            if (rank == 0) ws[t * D + tid] = h;             // replicated epi: one writer
        }
        __syncthreads();                                    // hsm ready for next step
        gp += G4;
    }
    // keep cluster smem alive until all in-flight st.async land
    asm volatile("barrier.cluster.arrive.aligned;" ::: "memory");
    asm volatile("barrier.cluster.wait.aligned;"   ::: "memory");
}

// ---------------- GAT ----------------

// Register-tiled GEMM: CTA = 64 rows x 128 cols, thread = 8 rows x 4 cols.
__global__ void __launch_bounds__(256, 2) k_gat_gemm(
    const float* __restrict__ nf_ext, int layer, const float* __restrict__ a_w)
{
    extern __shared__ float sh[];
    float* Wsm = sh;               // 16384 floats (64KB)
    float* Xs  = sh + D * D;       // 64*128 floats (32KB)
    float* av  = Xs + 64 * D;      // a_src[128], a_dst[128]
    int tid = threadIdx.x;

    const float4* Wg4 = (const float4*)(g_W + layer * D * D);
    float4* Wsm4 = (float4*)Wsm;
    for (int i = tid; i < D * D / 4; i += 256) Wsm4[i] = Wg4[i];

    const float* aw = a_w + layer * (2 * D + DE);
    if (tid < D) { av[tid] = aw[tid]; av[D + tid] = aw[D + DE + tid]; }

    const float* nf = layer ? g_feat : nf_ext;
    int row0 = blockIdx.x * 64;
    float4* Xs4 = (float4*)Xs;
    for (int i = tid; i < 64 * 32; i += 256) {
        int r = i >> 5, cc = i & 31;
        int gr = row0 + r;
        float4 v = make_float4(0.f, 0.f, 0.f, 0.f);
        if (gr < NN) v = ((const float4*)(nf + (size_t)gr * D))[cc];
        Xs4[i] = v;
    }
    __syncthreads();

    int lane = tid & 31, wid = tid >> 5;

    const float4* as4 = (const float4*)av;
    const float4* ad4 = (const float4*)(av + D);
#pragma unroll
    for (int i = 0; i < 8; i++) {
        int lr = wid * 8 + i;
        float4 x = Xs4[lr * 32 + lane];
        float4 a = as4[lane], b = ad4[lane];
        float ss = x.x * a.x + x.y * a.y + x.z * a.z + x.w * a.w;
        float sd = x.x * b.x + x.y * b.y + x.z * b.z + x.w * b.w;
#pragma unroll
        for (int o = 16; o; o >>= 1) {
            ss += __shfl_xor_sync(0xffffffffu, ss, o);
            sd += __shfl_xor_sync(0xffffffffu, sd, o);
        }
        int gr = row0 + lr;
        if (lane == 0 && gr < NN) { g_ssrc[gr] = ss; g_sdst[gr] = sd; }
    }

    const ulonglong2* W2 = (const ulonglong2*)Wsm;
    unsigned long long acc[8][2];
#pragma unroll
    for (int i = 0; i < 8; i++) { acc[i][0] = 0ull; acc[i][1] = 0ull; }

#pragma unroll 8
    for (int k4 = 0; k4 < 32; k4++) {
        ulonglong2 w0 = W2[(k4 * 4 + 0) * 32 + lane];
        ulonglong2 w1 = W2[(k4 * 4 + 1) * 32 + lane];
        ulonglong2 w2 = W2[(k4 * 4 + 2) * 32 + lane];
        ulonglong2 w3 = W2[(k4 * 4 + 3) * 32 + lane];
#pragma unroll
        for (int i = 0; i < 8; i++) {
            float4 xv = Xs4[(wid * 8 + i) * 32 + k4];
            unsigned long long xx;
            xx = dup2(xv.x);
            acc[i][0] = fma2(w0.x, xx, acc[i][0]); acc[i][1] = fma2(w0.y, xx, acc[i][1]);
            xx = dup2(xv.y);
            acc[i][0] = fma2(w1.x, xx, acc[i][0]); acc[i][1] = fma2(w1.y, xx, acc[i][1]);
            xx = dup2(xv.z);
            acc[i][0] = fma2(w2.x, xx, acc[i][0]); acc[i][1] = fma2(w2.y, xx, acc[i][1]);
            xx = dup2(xv.w);
            acc[i][0] = fma2(w3.x, xx, acc[i][0]); acc[i][1] = fma2(w3.y, xx, acc[i][1]);
        }
    }

#pragma unroll
    for (int i = 0; i < 8; i++) {
        int gr = row0 + wid * 8 + i;
        if (gr < NN) {
            float4 o;
            o.x = lo2(acc[i][0]); o.y = hi2(acc[i][0]);
            o.z = lo2(acc[i][1]); o.w = hi2(acc[i][1]);
            ((float4*)(g_ft + (size_t)gr * D))[lane] = o;
        }
    }
}

// fused per-node score + online softmax + aggregation: warp per dst node.
// dest + edot resolved IN DEVICE CODE (host-side &g_feat is garbage).
__global__ void __launch_bounds__(256) k_node_fused(
    float* __restrict__ dest_ext, int to_internal, int layer)
{
    int n = (blockIdx.x * 256 + threadIdx.x) >> 5;
    int lane = threadIdx.x & 31;
    if (n >= NN) return;
    float* dest = to_internal ? g_feat : dest_ext;
    int off = g_cnt[n], end = g_cnt[n + 1];
    float sdn = g_sdst[n];

    // pass 1: score + online max/denominator
    float m = -1e30f, den = 0.f;
    for (int j = off + lane; j < end; j += 32) {
        int s = g_ssorted[j];
        float2 ed = g_edot2[j];
        float sc = g_ssrc[s] + sdn + (layer ? ed.y : ed.x);
        g_sc2[j] = sc;
        if (sc > m) { den = den * __expf(m - sc) + 1.f; m = sc; }
        else den += __expf(sc - m);
    }
#pragma unroll
    for (int o = 16; o; o >>= 1) {
        float mo = __shfl_xor_sync(0xffffffffu, m, o);
        float dn = __shfl_xor_sync(0xffffffffu, den, o);
        float mn = fmaxf(m, mo);
        den = den * __expf(m - mn) + dn * __expf(mo - mn);
        m = mn;
    }
    float inv_den = den > 0.f ? __fdividef(1.f, den) : 0.f;

    // pass 2: aggregate (2-deep pipelined gather, packed fma2)
    unsigned long long acc0 = 0ull, acc1 = 0ull;
    for (int jb = off; jb < end; jb += 32) {
        int j = jb + lane;
        float al = 0.f; int sv = 0;
        if (j < end) {
            sv = g_ssorted[j];
            al = __expf(g_sc2[j] - m) * inv_den;
        }
        int cnt = min(32, end - jb);
        int k = 0;
        for (; k + 2 <= cnt; k += 2) {
            float a0f = __shfl_sync(0xffffffffu, al, k);
            float a1f = __shfl_sync(0xffffffffu, al, k + 1);
            int s0 = __shfl_sync(0xffffffffu, sv, k);
            int s1 = __shfl_sync(0xffffffffu, sv, k + 1);
            ulonglong2 v0 = ((const ulonglong2*)(g_ft + (size_t)s0 * D))[lane];
            ulonglong2 v1 = ((const ulonglong2*)(g_ft + (size_t)s1 * D))[lane];
            unsigned long long aa0 = dup2(a0f), aa1 = dup2(a1f);
            acc0 = fma2(v0.x, aa0, acc0); acc1 = fma2(v0.y, aa0, acc1);
            acc0 = fma2(v1.x, aa1, acc0); acc1 = fma2(v1.y, aa1, acc1);
        }
        if (k < cnt) {
            float a0f = __shfl_sync(0xffffffffu, al, k);
            int s0 = __shfl_sync(0xffffffffu, sv, k);
            ulonglong2 v0 = ((const ulonglong2*)(g_ft + (size_t)s0 * D))[lane];
            unsigned long long aa0 = dup2(a0f);
            acc0 = fma2(v0.x, aa0, acc0); acc1 = fma2(v0.y, aa0, acc1);
        }
    }
    float4 o;
    o.x = lo2(acc0); o.y = hi2(acc0); o.z = lo2(acc1); o.w = hi2(acc1);
    o.x = o.x >= 0.f ? o.x : 0.01f * o.x;
    o.y = o.y >= 0.f ? o.y : 0.01f * o.y;
    o.z = o.z >= 0.f ? o.z : 0.01f * o.z;
    o.w = o.w >= 0.f ? o.w : 0.01f * o.w;
    ((float4*)(dest + (size_t)n * D))[lane] = o;
}

// ---------------- launch ----------------
extern "C" void kernel_launch(void* const* d_in, const int* in_sizes, int n_in,
                              void* d_out, int out_size)
{
    const int*   src     = (const int*)  d_in[0];
    const int*   dst     = (const int*)  d_in[1];
    const float* n_feats = (const float*)d_in[2];
    const float* e_feats = (const float*)d_in[3];
    const float* W0      = (const float*)d_in[4];
    const float* Wih     = (const float*)d_in[5];
    const float* Whh     = (const float*)d_in[6];
    const float* bih     = (const float*)d_in[7];
    const float* bhh     = (const float*)d_in[8];
    const float* a_w     = (const float*)d_in[9];

    int n_edges = in_sizes[0] / 3;        // 800000
    int n_nodes = in_sizes[2] / (3 * D);  // 50000

    int smem_gemm = (D * D + 64 * D + 2 * D) * (int)sizeof(float);      // ~97KB
    cudaFuncSetAttribute(k_gat_gemm, cudaFuncAttributeMaxDynamicSharedMemorySize, smem_gemm);

    // only timestep j=2 matters for the output (feats never mix across j)
    const int*   src2 = src + 2 * n_edges;
    const int*   dst2 = dst + 2 * n_edges;
    const float* nf2  = n_feats + (size_t)2 * n_nodes * D;
    const float* ef2  = e_feats + (size_t)2 * n_edges * DE;

    // launch order keeps k_lstm_rec at ncu index 5 (-s 5 -c 1)
    k_zero_cnt<<<(NN + 256) / 256, 256>>>();                         // 0
    k_transpose_wih<<<(2 * G4 * D + 255) / 256, 256>>>(Wih);         // 1
    for (int call = 0; call < 3; call++) {
        k_lstm_g0<<<dim3(D / 4, 2), 512>>>(W0, call > 0, bih, bhh);  // 2,4,6
        k_lstm_rec<<<4, 1024>>>(Whh);                                // 3,5,7 (2 clusters of 2)
    }

    // dst-sorted edge structure + both layers' edge dots (needed only by fused)
    k_hist<<<(n_edges + 255) / 256, 256>>>(dst2);                    // 8
    k_scan<<<1, 1024>>>();                                           // 9
    k_scatter<<<(n_edges + 255) / 256, 256>>>(src2, dst2, ef2, a_w); // 10

    for (int layer = 0; layer < 2; layer++) {
        k_gat_gemm<<<(n_nodes + 63) / 64, 256, smem_gemm>>>(nf2, layer, a_w);
        k_node_fused<<<(n_nodes * 32 + 255) / 256, 256>>>((float*)d_out, layer == 0 ? 1 : 0, layer);
    }
}

// round 12
// speedup vs baseline: 1.5405x; 1.0433x over previous
#include <cuda_runtime.h>
#include <cuda_fp16.h>
#include <math.h>
#include <stdint.h>

#define NN 50000
#define NE 800000
#define D  128
#define DE 16
#define G4 512   // 4*D gates

// ---------------- scratch (static device globals; no allocation) ----------------
__device__ __align__(16) float g_W[2 * D * D];        // evolving LSTM state (hs) per layer
__device__ __align__(16) float g_G0[2 * D * G4];      // precomputed Wih@x + b per layer
__device__ __align__(16) float g_WihT[2 * D * G4];    // transposed Wih for coalesced G0 GEMM
__device__ __align__(16) uint2 g_ft2[(size_t)NN * 32];// nf @ W, packed fp16 (4 halves/uint2)
__device__ __align__(16) float g_feat[(size_t)NN * D];// layer-0 GAT output (post leaky)
__device__ float  g_sc2[NE];      // edge score in dst-sorted order
__device__ float2 g_edot2[NE];    // (layer0, layer1) ef @ a_edge, dst-sorted order
__device__ float  g_ssrc[NN];
__device__ float  g_sdst[NN];
// ---- dst-sorted edge structure (built once; graph identical across layers) ----
__device__ int g_cnt[NN + 1];     // counts -> exclusive offsets (in place)
__device__ int g_cur[NN];         // scatter cursors
__device__ int g_ssorted[NE];     // sorted position -> src node

// packed f32x2 FMA (sm_103a FFMA2) — PTX-only, ptxas won't auto-fuse
__device__ __forceinline__ unsigned long long fma2(
    unsigned long long a, unsigned long long b, unsigned long long c)
{
    unsigned long long d;
    asm("fma.rn.f32x2 %0, %1, %2, %3;" : "=l"(d) : "l"(a), "l"(b), "l"(c));
    return d;
}
__device__ __forceinline__ unsigned long long dup2(float x) {
    unsigned long long r;
    asm("mov.b64 %0, {%1,%1};" : "=l"(r) : "r"(__float_as_uint(x)));
    return r;
}
__device__ __forceinline__ float hsum2(unsigned long long a) {
    return __uint_as_float((unsigned)a) + __uint_as_float((unsigned)(a >> 32));
}
__device__ __forceinline__ float lo2(unsigned long long a) { return __uint_as_float((unsigned)a); }
__device__ __forceinline__ float hi2(unsigned long long a) { return __uint_as_float((unsigned)(a >> 32)); }
// f32x2 (lo,hi) -> f16x2 packed {lo,hi} in one cvt
__device__ __forceinline__ unsigned cvt_h2(unsigned long long f2) {
    unsigned r;
    asm("{ .reg .b32 lo, hi; mov.b64 {lo, hi}, %1; cvt.rn.f16x2.f32 %0, hi, lo; }"
        : "=r"(r) : "l"(f2));
    return r;
}
__device__ __forceinline__ float tanh_fast(float x) {
    float r; asm("tanh.approx.f32 %0, %1;" : "=f"(r) : "f"(x)); return r;
}
// sigmoid via single-MUFU tanh: sig(x) = 0.5*tanh(x/2) + 0.5
__device__ __forceinline__ float sig_fast(float x) {
    return fmaf(tanh_fast(0.5f * x), 0.5f, 0.5f);
}
__device__ __forceinline__ uint32_t smem_u32(const void* p) {
    uint32_t a;
    asm("{ .reg .u64 t; cvta.to.shared.u64 t, %1; cvt.u32.u64 %0, t; }" : "=r"(a) : "l"(p));
    return a;
}
__device__ __forceinline__ void mbar_wait_cluster(uint32_t mbar, uint32_t parity) {
    asm volatile(
        "{\n\t.reg .pred P1;\n\t"
        "WAIT_LOOP_%=:\n\t"
        "mbarrier.try_wait.parity.acquire.cluster.shared::cta.b64 P1, [%0], %1, 0x989680;\n\t"
        "@P1 bra.uni WAIT_DONE_%=;\n\t"
        "bra.uni WAIT_LOOP_%=;\n\t"
        "WAIT_DONE_%=:\n\t}"
        :: "r"(mbar), "r"(parity) : "memory");
}

// ---------------- edge sort (once) ----------------

__global__ void k_zero_cnt() {
    int idx = blockIdx.x * 256 + threadIdx.x;
    if (idx <= NN) g_cnt[idx] = 0;
}

__global__ void k_hist(const int* __restrict__ dst) {
    int e = blockIdx.x * 256 + threadIdx.x;
    if (e < NE) atomicAdd(&g_cnt[dst[e]], 1);
}

// single-CTA exclusive scan over 50k counts; writes offsets into g_cnt and g_cur
__global__ void __launch_bounds__(1024) k_scan() {
    const int CH = 49;                     // 1024*49 = 50176 >= NN
    int tid = threadIdx.x;
    int lane = tid & 31, wid = tid >> 5;
    int base = tid * CH;
    int s = 0;
    for (int i = 0; i < CH; i++) {
        int j = base + i;
        if (j < NN) s += g_cnt[j];
    }
    __shared__ int wsum[32];
    int v = s;
#pragma unroll
    for (int o = 1; o < 32; o <<= 1) {
        int t = __shfl_up_sync(0xffffffffu, v, o);
        if (lane >= o) v += t;
    }
    if (lane == 31) wsum[wid] = v;
    __syncthreads();
    if (wid == 0) {
        int w = wsum[lane];
#pragma unroll
        for (int o = 1; o < 32; o <<= 1) {
            int t = __shfl_up_sync(0xffffffffu, w, o);
            if (lane >= o) w += t;
        }
        wsum[lane] = w;
    }
    __syncthreads();
    int run = v - s + (wid ? wsum[wid - 1] : 0);   // exclusive prefix
    for (int i = 0; i < CH; i++) {
        int j = base + i;
        if (j < NN) {
            int c = g_cnt[j];
            g_cnt[j] = run;
            g_cur[j] = run;
            run += c;
        }
    }
    if (tid == 1023) g_cnt[NN] = NE;
}

// scatter + fused edge-feature dot for BOTH layers (ef read once, ever)
__global__ void __launch_bounds__(256) k_scatter(
    const int* __restrict__ src, const int* __restrict__ dst,
    const float* __restrict__ ef, const float* __restrict__ a_w)
{
    int e = blockIdx.x * 256 + threadIdx.x;
    if (e >= NE) return;
    int d = dst[e];
    int pos = atomicAdd(&g_cur[d], 1);
    g_ssorted[pos] = src[e];
    const float4* ep = (const float4*)(ef + (size_t)e * DE);
    const float* ae0 = a_w + D;
    const float* ae1 = a_w + (2 * D + DE) + D;
    float d0 = 0.f, d1 = 0.f;
#pragma unroll
    for (int i = 0; i < 4; i++) {
        float4 v = ep[i];
        d0 += v.x * __ldg(ae0 + i * 4)     + v.y * __ldg(ae0 + i * 4 + 1)
            + v.z * __ldg(ae0 + i * 4 + 2) + v.w * __ldg(ae0 + i * 4 + 3);
        d1 += v.x * __ldg(ae1 + i * 4)     + v.y * __ldg(ae1 + i * 4 + 1)
            + v.z * __ldg(ae1 + i * 4 + 2) + v.w * __ldg(ae1 + i * 4 + 3);
    }
    g_edot2[pos] = make_float2(d0, d1);
}

// ---------------- LSTM ----------------

// transpose Wih (L,512,128) -> WihT (L,128,512) for coalesced reads in G0
__global__ void k_transpose_wih(const float* __restrict__ Wih) {
    int idx = blockIdx.x * 256 + threadIdx.x;
    if (idx >= 2 * G4 * D) return;
    int layer = idx / (G4 * D);
    int rem   = idx - layer * (G4 * D);
    int g = rem / D, k = rem % D;
    g_WihT[(size_t)layer * (D * G4) + k * G4 + g] = Wih[idx];
}

// G0[t][g] = b[g] + sum_k X[t][k] * Wih[g][k]; 4 t-rows per block (WihT reuse 4x)
__global__ void __launch_bounds__(512) k_lstm_g0(
    const float* __restrict__ Xext, int use_state,
    const float* __restrict__ bih, const float* __restrict__ bhh)
{
    int layer = blockIdx.y;
    int t0 = blockIdx.x * 4;
    int g = threadIdx.x;
    __shared__ float xs[4 * D];
    const float* X = use_state ? (g_W + layer * D * D) : (Xext + layer * D * D);
    xs[g] = X[t0 * D + g];
    __syncthreads();
    const float* wt = g_WihT + (size_t)layer * (D * G4) + g;
    float b = bih[layer * G4 + g] + bhh[layer * G4 + g];
    float a0 = 0.f, a1 = 0.f, a2 = 0.f, a3 = 0.f;
#pragma unroll 4
    for (int k = 0; k < D; k++) {
        float w = wt[k * G4];
        a0 = fmaf(w, xs[k],         a0);
        a1 = fmaf(w, xs[D + k],     a1);
        a2 = fmaf(w, xs[2 * D + k], a2);
        a3 = fmaf(w, xs[3 * D + k], a3);
    }
    size_t o = (size_t)(layer * D + t0) * G4 + g;
    g_G0[o]          = a0 + b;
    g_G0[o + G4]     = a1 + b;
    g_G0[o + 2 * G4] = a2 + b;
    g_G0[o + 3 * G4] = a3 + b;
}

// 128-step recurrence, 2-CTA cluster per layer (grid=4, cluster=2).
// CTA rank R covers k in [R*64, R*64+64); W fully register-resident.
// Per step: FMA -> exchange 4KB raw partials via st.async+mbarrier
// (double-buffered by step parity) -> replicated epilogue in both CTAs.
__global__ void __launch_bounds__(1024, 1) __cluster_dims__(2, 1, 1)
k_lstm_rec(const float* __restrict__ Whh)
{
    __shared__ __align__(16) float hsm[D];
    __shared__ __align__(16) float praw_loc[1024];
    __shared__ __align__(16) float praw_rem[2][1024];   // double buffer (step parity)
    __shared__ __align__(8)  unsigned long long mbar_s;

    int tid = threadIdx.x;
    int layer = blockIdx.x >> 1;
    uint32_t rank;
    asm("mov.u32 %0, %%cluster_ctarank;" : "=r"(rank));
    uint32_t peer = rank ^ 1u;

    int half = tid >> 9;
    int r    = tid & 511;

    // this thread's 32 W floats -> 16 u64 registers
    const float* wrow = Whh + ((size_t)(layer * G4 + r)) * D + rank * 64 + half * 32;
    unsigned long long wreg[16];
#pragma unroll
    for (int j = 0; j < 16; j++)
        wreg[j] = *(const unsigned long long*)(wrow + 2 * j);

    uint32_t mbar_addr = smem_u32(&mbar_s);
    uint32_t rem_base  = smem_u32(&praw_rem[0][0]);
    uint32_t remote_base, remote_mbar;
    asm("mapa.shared::cluster.u32 %0, %1, %2;" : "=r"(remote_base) : "r"(rem_base), "r"(peer));
    asm("mapa.shared::cluster.u32 %0, %1, %2;" : "=r"(remote_mbar) : "r"(mbar_addr), "r"(peer));

    if (tid == 0)
        asm volatile("mbarrier.init.shared.b64 [%0], 1;" :: "r"(mbar_addr) : "memory");
    if (tid < D) hsm[tid] = 0.f;
    float c = 0.f;
    const float* g0 = g_G0 + (size_t)layer * (D * G4);
    float* ws = g_W + layer * D * D;
    __syncthreads();
    // mbarriers + hsm init must be cluster-visible before any peer st.async
    asm volatile("barrier.cluster.arrive.aligned;" ::: "memory");
    asm volatile("barrier.cluster.wait.aligned;"   ::: "memory");

    const ulonglong2* h2 = (const ulonglong2*)(hsm + rank * 64 + half * 32);
    uint32_t remote_dst0 = remote_base + tid * 4;           // buffer 0 slot
    const float* gp = g0 + tid;                             // epilogue g0 stream

    for (int t = 0; t < D; t++) {
        if (tid == 0)
            asm volatile("mbarrier.arrive.expect_tx.shared::cta.b64 _, [%0], 4096;"
                         :: "r"(mbar_addr) : "memory");
        // prefetch epilogue inputs (hidden under FMA)
        float q0, q1, q2, q3;
        if (tid < D) {
            q0 = __ldg(gp);       q1 = __ldg(gp + 128);
            q2 = __ldg(gp + 256); q3 = __ldg(gp + 384);
        }

        unsigned long long a0 = 0ull, a1 = 0ull;
#pragma unroll
        for (int j = 0; j < 8; j++) {
            ulonglong2 hh = h2[j];                          // warp-broadcast LDS
            a0 = fma2(wreg[2 * j],     hh.x, a0);
            a1 = fma2(wreg[2 * j + 1], hh.y, a1);
        }
        float own = hsum2(a0) + hsum2(a1);
        praw_loc[tid] = own;
        asm volatile("st.async.shared::cluster.mbarrier::complete_tx::bytes.b32 [%0], %1, [%2];"
                     :: "r"(remote_dst0 + (t & 1) * 4096), "r"(__float_as_uint(own)),
                        "r"(remote_mbar) : "memory");
        __syncthreads();                                    // praw_loc visible

        if (tid < D) {
            mbar_wait_cluster(mbar_addr, t & 1);            // peer's 4KB landed
            const float* pr = praw_rem[t & 1];
            float gi = q0 + praw_loc[tid]       + praw_loc[tid + 512]
                          + pr[tid]             + pr[tid + 512];
            float gf = q1 + praw_loc[tid + 128] + praw_loc[tid + 640]
                          + pr[tid + 128]       + pr[tid + 640];
            float gg = q2 + praw_loc[tid + 256] + praw_loc[tid + 768]
                          + pr[tid + 256]       + pr[tid + 768];
            float go = q3 + praw_loc[tid + 384] + praw_loc[tid + 896]
                          + pr[tid + 384]       + pr[tid + 896];
            float iv = sig_fast(gi), fv = sig_fast(gf);
            float gv = tanh_fast(gg), ov = sig_fast(go);
            c = fmaf(fv, c, iv * gv);
            float h = ov * tanh_fast(c);
            hsm[tid] = h;
            if (rank == 0) ws[t * D + tid] = h;             // replicated epi: one writer
        }
        __syncthreads();                                    // hsm ready for next step
        gp += G4;
    }
    // keep cluster smem alive until all in-flight st.async land
    asm volatile("barrier.cluster.arrive.aligned;" ::: "memory");
    asm volatile("barrier.cluster.wait.aligned;"   ::: "memory");
}

// ---------------- GAT ----------------

// Register-tiled GEMM: CTA = 64 rows x 128 cols, thread = 8 rows x 4 cols.
// Emits ft in packed fp16 (halves the aggregation gather traffic).
__global__ void __launch_bounds__(256, 2) k_gat_gemm(
    const float* __restrict__ nf_ext, int layer, const float* __restrict__ a_w)
{
    extern __shared__ float sh[];
    float* Wsm = sh;               // 16384 floats (64KB)
    float* Xs  = sh + D * D;       // 64*128 floats (32KB)
    float* av  = Xs + 64 * D;      // a_src[128], a_dst[128]
    int tid = threadIdx.x;

    const float4* Wg4 = (const float4*)(g_W + layer * D * D);
    float4* Wsm4 = (float4*)Wsm;
    for (int i = tid; i < D * D / 4; i += 256) Wsm4[i] = Wg4[i];

    const float* aw = a_w + layer * (2 * D + DE);
    if (tid < D) { av[tid] = aw[tid]; av[D + tid] = aw[D + DE + tid]; }

    const float* nf = layer ? g_feat : nf_ext;
    int row0 = blockIdx.x * 64;
    float4* Xs4 = (float4*)Xs;
    for (int i = tid; i < 64 * 32; i += 256) {
        int r = i >> 5, cc = i & 31;
        int gr = row0 + r;
        float4 v = make_float4(0.f, 0.f, 0.f, 0.f);
        if (gr < NN) v = ((const float4*)(nf + (size_t)gr * D))[cc];
        Xs4[i] = v;
    }
    __syncthreads();

    int lane = tid & 31, wid = tid >> 5;

    const float4* as4 = (const float4*)av;
    const float4* ad4 = (const float4*)(av + D);
#pragma unroll
    for (int i = 0; i < 8; i++) {
        int lr = wid * 8 + i;
        float4 x = Xs4[lr * 32 + lane];
        float4 a = as4[lane], b = ad4[lane];
        float ss = x.x * a.x + x.y * a.y + x.z * a.z + x.w * a.w;
        float sd = x.x * b.x + x.y * b.y + x.z * b.z + x.w * b.w;
#pragma unroll
        for (int o = 16; o; o >>= 1) {
            ss += __shfl_xor_sync(0xffffffffu, ss, o);
            sd += __shfl_xor_sync(0xffffffffu, sd, o);
        }
        int gr = row0 + lr;
        if (lane == 0 && gr < NN) { g_ssrc[gr] = ss; g_sdst[gr] = sd; }
    }

    const ulonglong2* W2 = (const ulonglong2*)Wsm;
    unsigned long long acc[8][2];
#pragma unroll
    for (int i = 0; i < 8; i++) { acc[i][0] = 0ull; acc[i][1] = 0ull; }

#pragma unroll 8
    for (int k4 = 0; k4 < 32; k4++) {
        ulonglong2 w0 = W2[(k4 * 4 + 0) * 32 + lane];
        ulonglong2 w1 = W2[(k4 * 4 + 1) * 32 + lane];
        ulonglong2 w2 = W2[(k4 * 4 + 2) * 32 + lane];
        ulonglong2 w3 = W2[(k4 * 4 + 3) * 32 + lane];
#pragma unroll
        for (int i = 0; i < 8; i++) {
            float4 xv = Xs4[(wid * 8 + i) * 32 + k4];
            unsigned long long xx;
            xx = dup2(xv.x);
            acc[i][0] = fma2(w0.x, xx, acc[i][0]); acc[i][1] = fma2(w0.y, xx, acc[i][1]);
            xx = dup2(xv.y);
            acc[i][0] = fma2(w1.x, xx, acc[i][0]); acc[i][1] = fma2(w1.y, xx, acc[i][1]);
            xx = dup2(xv.z);
            acc[i][0] = fma2(w2.x, xx, acc[i][0]); acc[i][1] = fma2(w2.y, xx, acc[i][1]);
            xx = dup2(xv.w);
            acc[i][0] = fma2(w3.x, xx, acc[i][0]); acc[i][1] = fma2(w3.y, xx, acc[i][1]);
        }
    }

#pragma unroll
    for (int i = 0; i < 8; i++) {
        int gr = row0 + wid * 8 + i;
        if (gr < NN)
            g_ft2[(size_t)gr * 32 + lane] =
                make_uint2(cvt_h2(acc[i][0]), cvt_h2(acc[i][1]));
    }
}

// fused per-node score + online softmax + aggregation: warp per dst node.
// ft gathered as fp16 (8B/lane), accumulated in fp32.
// dest resolved IN DEVICE CODE (host-side &g_feat is garbage).
__global__ void __launch_bounds__(256) k_node_fused(
    float* __restrict__ dest_ext, int to_internal, int layer)
{
    int n = (blockIdx.x * 256 + threadIdx.x) >> 5;
    int lane = threadIdx.x & 31;
    if (n >= NN) return;
    float* dest = to_internal ? g_feat : dest_ext;
    int off = g_cnt[n], end = g_cnt[n + 1];
    float sdn = g_sdst[n];

    // pass 1: score + online max/denominator
    float m = -1e30f, den = 0.f;
    for (int j = off + lane; j < end; j += 32) {
        int s = g_ssorted[j];
        float2 ed = g_edot2[j];
        float sc = g_ssrc[s] + sdn + (layer ? ed.y : ed.x);
        g_sc2[j] = sc;
        if (sc > m) { den = den * __expf(m - sc) + 1.f; m = sc; }
        else den += __expf(sc - m);
    }
#pragma unroll
    for (int o = 16; o; o >>= 1) {
        float mo = __shfl_xor_sync(0xffffffffu, m, o);
        float dn = __shfl_xor_sync(0xffffffffu, den, o);
        float mn = fmaxf(m, mo);
        den = den * __expf(m - mn) + dn * __expf(mo - mn);
        m = mn;
    }
    float inv_den = den > 0.f ? __fdividef(1.f, den) : 0.f;

    // pass 2: aggregate (2-deep pipelined fp16 gather, fp32 accumulate)
    float4 acc = make_float4(0.f, 0.f, 0.f, 0.f);
    for (int jb = off; jb < end; jb += 32) {
        int j = jb + lane;
        float al = 0.f; int sv = 0;
        if (j < end) {
            sv = g_ssorted[j];
            al = __expf(g_sc2[j] - m) * inv_den;
        }
        int cnt = min(32, end - jb);
        int k = 0;
        for (; k + 2 <= cnt; k += 2) {
            float a0f = __shfl_sync(0xffffffffu, al, k);
            float a1f = __shfl_sync(0xffffffffu, al, k + 1);
            int s0 = __shfl_sync(0xffffffffu, sv, k);
            int s1 = __shfl_sync(0xffffffffu, sv, k + 1);
            uint2 v0 = g_ft2[(size_t)s0 * 32 + lane];
            uint2 v1 = g_ft2[(size_t)s1 * 32 + lane];
            float2 f00 = __half22float2(*(__half2*)&v0.x);
            float2 f01 = __half22float2(*(__half2*)&v0.y);
            float2 f10 = __half22float2(*(__half2*)&v1.x);
            float2 f11 = __half22float2(*(__half2*)&v1.y);
            acc.x = fmaf(a0f, f00.x, acc.x); acc.y = fmaf(a0f, f00.y, acc.y);
            acc.z = fmaf(a0f, f01.x, acc.z); acc.w = fmaf(a0f, f01.y, acc.w);
            acc.x = fmaf(a1f, f10.x, acc.x); acc.y = fmaf(a1f, f10.y, acc.y);
            acc.z = fmaf(a1f, f11.x, acc.z); acc.w = fmaf(a1f, f11.y, acc.w);
        }
        if (k < cnt) {
            float a0f = __shfl_sync(0xffffffffu, al, k);
            int s0 = __shfl_sync(0xffffffffu, sv, k);
            uint2 v0 = g_ft2[(size_t)s0 * 32 + lane];
            float2 f00 = __half22float2(*(__half2*)&v0.x);
            float2 f01 = __half22float2(*(__half2*)&v0.y);
            acc.x = fmaf(a0f, f00.x, acc.x); acc.y = fmaf(a0f, f00.y, acc.y);
            acc.z = fmaf(a0f, f01.x, acc.z); acc.w = fmaf(a0f, f01.y, acc.w);
        }
    }
    acc.x = acc.x >= 0.f ? acc.x : 0.01f * acc.x;
    acc.y = acc.y >= 0.f ? acc.y : 0.01f * acc.y;
    acc.z = acc.z >= 0.f ? acc.z : 0.01f * acc.z;
    acc.w = acc.w >= 0.f ? acc.w : 0.01f * acc.w;
    ((float4*)(dest + (size_t)n * D))[lane] = acc;
}

// ---------------- launch ----------------
extern "C" void kernel_launch(void* const* d_in, const int* in_sizes, int n_in,
                              void* d_out, int out_size)
{
    const int*   src     = (const int*)  d_in[0];
    const int*   dst     = (const int*)  d_in[1];
    const float* n_feats = (const float*)d_in[2];
    const float* e_feats = (const float*)d_in[3];
    const float* W0      = (const float*)d_in[4];
    const float* Wih     = (const float*)d_in[5];
    const float* Whh     = (const float*)d_in[6];
    const float* bih     = (const float*)d_in[7];
    const float* bhh     = (const float*)d_in[8];
    const float* a_w     = (const float*)d_in[9];

    int n_edges = in_sizes[0] / 3;        // 800000
    int n_nodes = in_sizes[2] / (3 * D);  // 50000

    int smem_gemm = (D * D + 64 * D + 2 * D) * (int)sizeof(float);      // ~97KB
    cudaFuncSetAttribute(k_gat_gemm, cudaFuncAttributeMaxDynamicSharedMemorySize, smem_gemm);

    // only timestep j=2 matters for the output (feats never mix across j)
    const int*   src2 = src + 2 * n_edges;
    const int*   dst2 = dst + 2 * n_edges;
    const float* nf2  = n_feats + (size_t)2 * n_nodes * D;
    const float* ef2  = e_feats + (size_t)2 * n_edges * DE;

    // launch order keeps k_lstm_rec at ncu index 5 (-s 5 -c 1)
    k_zero_cnt<<<(NN + 256) / 256, 256>>>();                         // 0
    k_transpose_wih<<<(2 * G4 * D + 255) / 256, 256>>>(Wih);         // 1
    for (int call = 0; call < 3; call++) {
        k_lstm_g0<<<dim3(D / 4, 2), 512>>>(W0, call > 0, bih, bhh);  // 2,4,6
        k_lstm_rec<<<4, 1024>>>(Whh);                                // 3,5,7 (2 clusters of 2)
    }

    // dst-sorted edge structure + both layers' edge dots (needed only by fused)
    k_hist<<<(n_edges + 255) / 256, 256>>>(dst2);                    // 8
    k_scan<<<1, 1024>>>();                                           // 9
    k_scatter<<<(n_edges + 255) / 256, 256>>>(src2, dst2, ef2, a_w); // 10

    for (int layer = 0; layer < 2; layer++) {
        k_gat_gemm<<<(n_nodes + 63) / 64, 256, smem_gemm>>>(nf2, layer, a_w);
        k_node_fused<<<(n_nodes * 32 + 255) / 256, 256>>>((float*)d_out, layer == 0 ? 1 : 0, layer);
    }
}

// round 16
// speedup vs baseline: 1.5896x; 1.0318x over previous
#include <cuda_runtime.h>
#include <cuda_fp16.h>
#include <math.h>
#include <stdint.h>

#define NN 50000
#define NE 800000
#define D  128
#define DE 16
#define G4 512   // 4*D gates

// ---------------- scratch (static device globals; no allocation) ----------------
__device__ __align__(16) float g_W[2 * D * D];        // evolving LSTM state (hs) per layer
__device__ __align__(16) float g_G0[2 * D * G4];      // precomputed Wih@x + b per layer
__device__ __align__(16) float g_WihT[2 * D * G4];    // transposed Wih for coalesced G0 GEMM
__device__ __align__(16) uint2 g_ft2[(size_t)NN * 32];// nf @ W, packed fp16 (4 halves/uint2)
__device__ __align__(16) float g_feat[(size_t)NN * D];// layer-0 GAT output (post leaky)
__device__ float  g_sc2[NE];      // edge score in dst-sorted order
__device__ float2 g_edot2[NE];    // (layer0, layer1) ef @ a_edge, dst-sorted order
__device__ float  g_ssrc[NN];
__device__ float  g_sdst[NN];
// ---- dst-sorted edge structure (built under the LSTM; graph same across layers) ----
__device__ int g_cnt[NN + 1];     // counts -> exclusive offsets (in place)
__device__ int g_cur[NN];         // scatter cursors
__device__ int g_ssorted[NE];     // sorted position -> src node

// packed f32x2 FMA (sm_103a FFMA2) — PTX-only, ptxas won't auto-fuse
__device__ __forceinline__ unsigned long long fma2(
    unsigned long long a, unsigned long long b, unsigned long long c)
{
    unsigned long long d;
    asm("fma.rn.f32x2 %0, %1, %2, %3;" : "=l"(d) : "l"(a), "l"(b), "l"(c));
    return d;
}
__device__ __forceinline__ unsigned long long dup2(float x) {
    unsigned long long r;
    asm("mov.b64 %0, {%1,%1};" : "=l"(r) : "r"(__float_as_uint(x)));
    return r;
}
__device__ __forceinline__ float hsum2(unsigned long long a) {
    return __uint_as_float((unsigned)a) + __uint_as_float((unsigned)(a >> 32));
}
__device__ __forceinline__ float lo2(unsigned long long a) { return __uint_as_float((unsigned)a); }
__device__ __forceinline__ float hi2(unsigned long long a) { return __uint_as_float((unsigned)(a >> 32)); }
// f32x2 (lo,hi) -> f16x2 packed {lo,hi} in one cvt
__device__ __forceinline__ unsigned cvt_h2(unsigned long long f2) {
    unsigned r;
    asm("{ .reg .b32 lo, hi; mov.b64 {lo, hi}, %1; cvt.rn.f16x2.f32 %0, hi, lo; }"
        : "=r"(r) : "l"(f2));
    return r;
}
__device__ __forceinline__ float tanh_fast(float x) {
    float r; asm("tanh.approx.f32 %0, %1;" : "=f"(r) : "f"(x)); return r;
}
// sigmoid via single-MUFU tanh: sig(x) = 0.5*tanh(x/2) + 0.5
__device__ __forceinline__ float sig_fast(float x) {
    return fmaf(tanh_fast(0.5f * x), 0.5f, 0.5f);
}
__device__ __forceinline__ uint32_t smem_u32(const void* p) {
    uint32_t a;
    asm("{ .reg .u64 t; cvta.to.shared.u64 t, %1; cvt.u32.u64 %0, t; }" : "=r"(a) : "l"(p));
    return a;
}
__device__ __forceinline__ void mbar_wait_cluster(uint32_t mbar, uint32_t parity) {
    asm volatile(
        "{\n\t.reg .pred P1;\n\t"
        "WAIT_LOOP_%=:\n\t"
        "mbarrier.try_wait.parity.acquire.cluster.shared::cta.b64 P1, [%0], %1, 0x989680;\n\t"
        "@P1 bra.uni WAIT_DONE_%=;\n\t"
        "bra.uni WAIT_LOOP_%=;\n\t"
        "WAIT_DONE_%=:\n\t}"
        :: "r"(mbar), "r"(parity) : "memory");
}

// ---------------- LSTM (+ sort work piggybacked on idle SMs) ----------------

__global__ void k_zero_cnt() {
    int idx = blockIdx.x * 256 + threadIdx.x;
    if (idx <= NN) g_cnt[idx] = 0;
}

// transpose Wih (L,512,128) -> WihT (L,128,512) for coalesced reads in G0
__global__ void k_transpose_wih(const float* __restrict__ Wih) {
    int idx = blockIdx.x * 256 + threadIdx.x;
    if (idx >= 2 * G4 * D) return;
    int layer = idx / (G4 * D);
    int rem   = idx - layer * (G4 * D);
    int g = rem / D, k = rem % D;
    g_WihT[(size_t)layer * (D * G4) + k * G4 + g] = Wih[idx];
}

// G0[t][g] = b[g] + sum_k X[t][k] * Wih[g][k]; 4 t-rows per block (WihT reuse 4x)
__global__ void __launch_bounds__(512) k_lstm_g0(
    const float* __restrict__ Xext, int use_state,
    const float* __restrict__ bih, const float* __restrict__ bhh)
{
    int layer = blockIdx.y;
    int t0 = blockIdx.x * 4;
    int g = threadIdx.x;
    __shared__ float xs[4 * D];
    const float* X = use_state ? (g_W + layer * D * D) : (Xext + layer * D * D);
    xs[g] = X[t0 * D + g];
    __syncthreads();
    const float* wt = g_WihT + (size_t)layer * (D * G4) + g;
    float b = bih[layer * G4 + g] + bhh[layer * G4 + g];
    float a0 = 0.f, a1 = 0.f, a2 = 0.f, a3 = 0.f;
#pragma unroll 4
    for (int k = 0; k < D; k++) {
        float w = wt[k * G4];
        a0 = fmaf(w, xs[k],         a0);
        a1 = fmaf(w, xs[D + k],     a1);
        a2 = fmaf(w, xs[2 * D + k], a2);
        a3 = fmaf(w, xs[3 * D + k], a3);
    }
    size_t o = (size_t)(layer * D + t0) * G4 + g;
    g_G0[o]          = a0 + b;
    g_G0[o + G4]     = a1 + b;
    g_G0[o + 2 * G4] = a2 + b;
    g_G0[o + 3 * G4] = a3 + b;
}

// 128-step recurrence, 2-CTA cluster per layer (CTAs 0..3), W register-resident.
// Row's two k-halves sit in ADJACENT LANES (tid = r*2+half): one shfl pre-reduces,
// only even lanes st.async 2KB to the peer (double-buffered by step parity).
// CTAs >= 4 run the dst-sort pipeline on otherwise-idle SMs:
//   phase 0: histogram   phase 1: scan (single CTA)   phase 2: scatter + edge dots
__global__ void __launch_bounds__(1024, 1) __cluster_dims__(2, 1, 1)
k_lstm_rec(const float* __restrict__ Whh, int phase,
           const int* __restrict__ src, const int* __restrict__ dst,
           const float* __restrict__ ef, const float* __restrict__ a_w)
{
    __shared__ __align__(16) float hsm[D];
    __shared__ __align__(16) float praw_loc[512];
    __shared__ __align__(16) float praw_rem[2][512];    // double buffer (step parity)
    __shared__ __align__(8)  unsigned long long mbar_s;
    __shared__ int wsum[32];

    int tid = threadIdx.x;

    // ---------- piggybacked sort work on extra CTAs ----------
    if (blockIdx.x >= 4) {
        int xb = blockIdx.x - 4;
        if (phase == 0) {                       // histogram
            int e = xb * 1024 + tid;
            if (e < NE) atomicAdd(&g_cnt[dst[e]], 1);
        } else if (phase == 1) {                // exclusive scan (single CTA)
            if (xb != 0) return;
            const int CH = 49;
            int lane = tid & 31, wid = tid >> 5;
            int base = tid * CH;
            int s = 0;
            for (int i = 0; i < CH; i++) {
                int j = base + i;
                if (j < NN) s += g_cnt[j];
            }
            int v = s;
#pragma unroll
            for (int o = 1; o < 32; o <<= 1) {
                int t = __shfl_up_sync(0xffffffffu, v, o);
                if (lane >= o) v += t;
            }
            if (lane == 31) wsum[wid] = v;
            __syncthreads();
            if (wid == 0) {
                int w = wsum[lane];
#pragma unroll
                for (int o = 1; o < 32; o <<= 1) {
                    int t = __shfl_up_sync(0xffffffffu, w, o);
                    if (lane >= o) w += t;
                }
                wsum[lane] = w;
            }
            __syncthreads();
            int run = v - s + (wid ? wsum[wid - 1] : 0);
            for (int i = 0; i < CH; i++) {
                int j = base + i;
                if (j < NN) {
                    int c = g_cnt[j];
                    g_cnt[j] = run;
                    g_cur[j] = run;
                    run += c;
                }
            }
            if (tid == 1023) g_cnt[NN] = NE;
        } else {                                // scatter + both layers' edge dots
            int e = xb * 1024 + tid;
            if (e < NE) {
                int d = dst[e];
                int pos = atomicAdd(&g_cur[d], 1);
                g_ssorted[pos] = src[e];
                const float4* ep = (const float4*)(ef + (size_t)e * DE);
                const float* ae0 = a_w + D;
                const float* ae1 = a_w + (2 * D + DE) + D;
                float d0 = 0.f, d1 = 0.f;
#pragma unroll
                for (int i = 0; i < 4; i++) {
                    float4 v = ep[i];
                    d0 += v.x * __ldg(ae0 + i * 4)     + v.y * __ldg(ae0 + i * 4 + 1)
                        + v.z * __ldg(ae0 + i * 4 + 2) + v.w * __ldg(ae0 + i * 4 + 3);
                    d1 += v.x * __ldg(ae1 + i * 4)     + v.y * __ldg(ae1 + i * 4 + 1)
                        + v.z * __ldg(ae1 + i * 4 + 2) + v.w * __ldg(ae1 + i * 4 + 3);
                }
                g_edot2[pos] = make_float2(d0, d1);
            }
        }
        return;
    }

    // ---------- LSTM recurrence (CTAs 0..3) ----------
    int layer = blockIdx.x >> 1;
    uint32_t rank;
    asm("mov.u32 %0, %%cluster_ctarank;" : "=r"(rank));
    uint32_t peer = rank ^ 1u;

    int r    = tid >> 1;          // gate row 0..511
    int half = tid & 1;           // k-half within this CTA's 64 k's

    // this thread's 32 W floats -> 16 u64 registers
    const float* wrow = Whh + ((size_t)(layer * G4 + r)) * D + rank * 64 + half * 32;
    unsigned long long wreg[16];
#pragma unroll
    for (int j = 0; j < 16; j++)
        wreg[j] = *(const unsigned long long*)(wrow + 2 * j);

    uint32_t mbar_addr = smem_u32(&mbar_s);
    uint32_t rem_base  = smem_u32(&praw_rem[0][0]);
    uint32_t remote_base, remote_mbar;
    asm("mapa.shared::cluster.u32 %0, %1, %2;" : "=r"(remote_base) : "r"(rem_base), "r"(peer));
    asm("mapa.shared::cluster.u32 %0, %1, %2;" : "=r"(remote_mbar) : "r"(mbar_addr), "r"(peer));

    if (tid == 0)
        asm volatile("mbarrier.init.shared.b64 [%0], 1;" :: "r"(mbar_addr) : "memory");
    if (tid < D) hsm[tid] = 0.f;
    float c = 0.f;
    const float* g0 = g_G0 + (size_t)layer * (D * G4);
    float* ws = g_W + layer * D * D;
    __syncthreads();
    // mbarriers + hsm init must be cluster-visible before any peer st.async
    asm volatile("barrier.cluster.arrive.aligned;" ::: "memory");
    asm volatile("barrier.cluster.wait.aligned;"   ::: "memory");

    const ulonglong2* h2 = (const ulonglong2*)(hsm + rank * 64 + half * 32);
    uint32_t remote_dst0 = remote_base + r * 4;             // buffer 0 slot (even lanes)
    const float* gp = g0 + tid;                             // epilogue g0 stream

    for (int t = 0; t < D; t++) {
        if (tid == 0)
            asm volatile("mbarrier.arrive.expect_tx.shared::cta.b64 _, [%0], 2048;"
                         :: "r"(mbar_addr) : "memory");
        // prefetch epilogue inputs (hidden under FMA)
        float q0, q1, q2, q3;
        if (tid < D) {
            q0 = __ldg(gp);       q1 = __ldg(gp + 128);
            q2 = __ldg(gp + 256); q3 = __ldg(gp + 384);
        }

        unsigned long long a0 = 0ull, a1 = 0ull;
#pragma unroll
        for (int j = 0; j < 8; j++) {
            ulonglong2 hh = h2[j];                          // 2-way broadcast LDS
            a0 = fma2(wreg[2 * j],     hh.x, a0);
            a1 = fma2(wreg[2 * j + 1], hh.y, a1);
        }
        float own = hsum2(a0) + hsum2(a1);
        float comb = own + __shfl_down_sync(0xffffffffu, own, 1);
        if (!half) {                                        // even lane: full local row sum
            praw_loc[r] = comb;
            asm volatile("st.async.shared::cluster.mbarrier::complete_tx::bytes.b32 [%0], %1, [%2];"
                         :: "r"(remote_dst0 + (t & 1) * 2048), "r"(__float_as_uint(comb)),
                            "r"(remote_mbar) : "memory");
        }
        __syncthreads();                                    // praw_loc visible

        if (tid < D) {
            mbar_wait_cluster(mbar_addr, t & 1);            // peer's 2KB landed
            const float* pr = praw_rem[t & 1];
            float gi = q0 + praw_loc[tid]       + pr[tid];
            float gf = q1 + praw_loc[tid + 128] + pr[tid + 128];
            float gg = q2 + praw_loc[tid + 256] + pr[tid + 256];
            float go = q3 + praw_loc[tid + 384] + pr[tid + 384];
            float iv = sig_fast(gi), fv = sig_fast(gf);
            float gv = tanh_fast(gg), ov = sig_fast(go);
            c = fmaf(fv, c, iv * gv);
            float h = ov * tanh_fast(c);
            hsm[tid] = h;
            if (rank == 0) ws[t * D + tid] = h;             // replicated epi: one writer
        }
        __syncthreads();                                    // hsm ready for next step
        gp += G4;
    }
    // keep cluster smem alive until all in-flight st.async land
    asm volatile("barrier.cluster.arrive.aligned;" ::: "memory");
    asm volatile("barrier.cluster.wait.aligned;"   ::: "memory");
}

// ---------------- GAT ----------------

// Register-tiled GEMM: CTA = 64 rows x 128 cols, thread = 8 rows x 4 cols.
// Emits ft in packed fp16 (halves the aggregation gather traffic).
__global__ void __launch_bounds__(256, 2) k_gat_gemm(
    const float* __restrict__ nf_ext, int layer, const float* __restrict__ a_w)
{
    extern __shared__ float sh[];
    float* Wsm = sh;               // 16384 floats (64KB)
    float* Xs  = sh + D * D;       // 64*128 floats (32KB)
    float* av  = Xs + 64 * D;      // a_src[128], a_dst[128]
    int tid = threadIdx.x;

    const float4* Wg4 = (const float4*)(g_W + layer * D * D);
    float4* Wsm4 = (float4*)Wsm;
    for (int i = tid; i < D * D / 4; i += 256) Wsm4[i] = Wg4[i];

    const float* aw = a_w + layer * (2 * D + DE);
    if (tid < D) { av[tid] = aw[tid]; av[D + tid] = aw[D + DE + tid]; }

    const float* nf = layer ? g_feat : nf_ext;
    int row0 = blockIdx.x * 64;
    float4* Xs4 = (float4*)Xs;
    for (int i = tid; i < 64 * 32; i += 256) {
        int r = i >> 5, cc = i & 31;
        int gr = row0 + r;
        float4 v = make_float4(0.f, 0.f, 0.f, 0.f);
        if (gr < NN) v = ((const float4*)(nf + (size_t)gr * D))[cc];
        Xs4[i] = v;
    }
    __syncthreads();

    int lane = tid & 31, wid = tid >> 5;

    const float4* as4 = (const float4*)av;
    const float4* ad4 = (const float4*)(av + D);
#pragma unroll
    for (int i = 0; i < 8; i++) {
        int lr = wid * 8 + i;
        float4 x = Xs4[lr * 32 + lane];
        float4 a = as4[lane], b = ad4[lane];
        float ss = x.x * a.x + x.y * a.y + x.z * a.z + x.w * a.w;
        float sd = x.x * b.x + x.y * b.y + x.z * b.z + x.w * b.w;
#pragma unroll
        for (int o = 16; o; o >>= 1) {
            ss += __shfl_xor_sync(0xffffffffu, ss, o);
            sd += __shfl_xor_sync(0xffffffffu, sd, o);
        }
        int gr = row0 + lr;
        if (lane == 0 && gr < NN) { g_ssrc[gr] = ss; g_sdst[gr] = sd; }
    }

    const ulonglong2* W2 = (const ulonglong2*)Wsm;
    unsigned long long acc[8][2];
#pragma unroll
    for (int i = 0; i < 8; i++) { acc[i][0] = 0ull; acc[i][1] = 0ull; }

#pragma unroll 8
    for (int k4 = 0; k4 < 32; k4++) {
        ulonglong2 w0 = W2[(k4 * 4 + 0) * 32 + lane];
        ulonglong2 w1 = W2[(k4 * 4 + 1) * 32 + lane];
        ulonglong2 w2 = W2[(k4 * 4 + 2) * 32 + lane];
        ulonglong2 w3 = W2[(k4 * 4 + 3) * 32 + lane];
#pragma unroll
        for (int i = 0; i < 8; i++) {
            float4 xv = Xs4[(wid * 8 + i) * 32 + k4];
            unsigned long long xx;
            xx = dup2(xv.x);
            acc[i][0] = fma2(w0.x, xx, acc[i][0]); acc[i][1] = fma2(w0.y, xx, acc[i][1]);
            xx = dup2(xv.y);
            acc[i][0] = fma2(w1.x, xx, acc[i][0]); acc[i][1] = fma2(w1.y, xx, acc[i][1]);
            xx = dup2(xv.z);
            acc[i][0] = fma2(w2.x, xx, acc[i][0]); acc[i][1] = fma2(w2.y, xx, acc[i][1]);
            xx = dup2(xv.w);
            acc[i][0] = fma2(w3.x, xx, acc[i][0]); acc[i][1] = fma2(w3.y, xx, acc[i][1]);
        }
    }

#pragma unroll
    for (int i = 0; i < 8; i++) {
        int gr = row0 + wid * 8 + i;
        if (gr < NN)
            g_ft2[(size_t)gr * 32 + lane] =
                make_uint2(cvt_h2(acc[i][0]), cvt_h2(acc[i][1]));
    }
}

// fused per-node score + online softmax + aggregation: warp per dst node.
// ft gathered as fp16 (8B/lane), accumulated in fp32.
// dest resolved IN DEVICE CODE (host-side &g_feat is garbage).
__global__ void __launch_bounds__(256) k_node_fused(
    float* __restrict__ dest_ext, int to_internal, int layer)
{
    int n = (blockIdx.x * 256 + threadIdx.x) >> 5;
    int lane = threadIdx.x & 31;
    if (n >= NN) return;
    float* dest = to_internal ? g_feat : dest_ext;
    int off = g_cnt[n], end = g_cnt[n + 1];
    float sdn = g_sdst[n];

    // pass 1: score + online max/denominator
    float m = -1e30f, den = 0.f;
    for (int j = off + lane; j < end; j += 32) {
        int s = g_ssorted[j];
        float2 ed = g_edot2[j];
        float sc = g_ssrc[s] + sdn + (layer ? ed.y : ed.x);
        g_sc2[j] = sc;
        if (sc > m) { den = den * __expf(m - sc) + 1.f; m = sc; }
        else den += __expf(sc - m);
    }
#pragma unroll
    for (int o = 16; o; o >>= 1) {
        float mo = __shfl_xor_sync(0xffffffffu, m, o);
        float dn = __shfl_xor_sync(0xffffffffu, den, o);
        float mn = fmaxf(m, mo);
        den = den * __expf(m - mn) + dn * __expf(mo - mn);
        m = mn;
    }
    float inv_den = den > 0.f ? __fdividef(1.f, den) : 0.f;

    // pass 2: aggregate (2-deep pipelined fp16 gather, fp32 accumulate)
    float4 acc = make_float4(0.f, 0.f, 0.f, 0.f);
    for (int jb = off; jb < end; jb += 32) {
        int j = jb + lane;
        float al = 0.f; int sv = 0;
        if (j < end) {
            sv = g_ssorted[j];
            al = __expf(g_sc2[j] - m) * inv_den;
        }
        int cnt = min(32, end - jb);
        int k = 0;
        for (; k + 2 <= cnt; k += 2) {
            float a0f = __shfl_sync(0xffffffffu, al, k);
            float a1f = __shfl_sync(0xffffffffu, al, k + 1);
            int s0 = __shfl_sync(0xffffffffu, sv, k);
            int s1 = __shfl_sync(0xffffffffu, sv, k + 1);
            uint2 v0 = g_ft2[(size_t)s0 * 32 + lane];
            uint2 v1 = g_ft2[(size_t)s1 * 32 + lane];
            float2 f00 = __half22float2(*(__half2*)&v0.x);
            float2 f01 = __half22float2(*(__half2*)&v0.y);
            float2 f10 = __half22float2(*(__half2*)&v1.x);
            float2 f11 = __half22float2(*(__half2*)&v1.y);
            acc.x = fmaf(a0f, f00.x, acc.x); acc.y = fmaf(a0f, f00.y, acc.y);
            acc.z = fmaf(a0f, f01.x, acc.z); acc.w = fmaf(a0f, f01.y, acc.w);
            acc.x = fmaf(a1f, f10.x, acc.x); acc.y = fmaf(a1f, f10.y, acc.y);
            acc.z = fmaf(a1f, f11.x, acc.z); acc.w = fmaf(a1f, f11.y, acc.w);
        }
        if (k < cnt) {
            float a0f = __shfl_sync(0xffffffffu, al, k);
            int s0 = __shfl_sync(0xffffffffu, sv, k);
            uint2 v0 = g_ft2[(size_t)s0 * 32 + lane];
            float2 f00 = __half22float2(*(__half2*)&v0.x);
            float2 f01 = __half22float2(*(__half2*)&v0.y);
            acc.x = fmaf(a0f, f00.x, acc.x); acc.y = fmaf(a0f, f00.y, acc.y);
            acc.z = fmaf(a0f, f01.x, acc.z); acc.w = fmaf(a0f, f01.y, acc.w);
        }
    }
    acc.x = acc.x >= 0.f ? acc.x : 0.01f * acc.x;
    acc.y = acc.y >= 0.f ? acc.y : 0.01f * acc.y;
    acc.z = acc.z >= 0.f ? acc.z : 0.01f * acc.z;
    acc.w = acc.w >= 0.f ? acc.w : 0.01f * acc.w;
    ((float4*)(dest + (size_t)n * D))[lane] = acc;
}

// ---------------- launch ----------------
extern "C" void kernel_launch(void* const* d_in, const int* in_sizes, int n_in,
                              void* d_out, int out_size)
{
    const int*   src     = (const int*)  d_in[0];
    const int*   dst     = (const int*)  d_in[1];
    const float* n_feats = (const float*)d_in[2];
    const float* e_feats = (const float*)d_in[3];
    const float* W0      = (const float*)d_in[4];
    const float* Wih     = (const float*)d_in[5];
    const float* Whh     = (const float*)d_in[6];
    const float* bih     = (const float*)d_in[7];
    const float* bhh     = (const float*)d_in[8];
    const float* a_w     = (const float*)d_in[9];

    int n_edges = in_sizes[0] / 3;        // 800000
    int n_nodes = in_sizes[2] / (3 * D);  // 50000

    int smem_gemm = (D * D + 64 * D + 2 * D) * (int)sizeof(float);      // ~97KB
    cudaFuncSetAttribute(k_gat_gemm, cudaFuncAttributeMaxDynamicSharedMemorySize, smem_gemm);

    // only timestep j=2 matters for the output (feats never mix across j)
    const int*   src2 = src + 2 * n_edges;
    const int*   dst2 = dst + 2 * n_edges;
    const float* nf2  = n_feats + (size_t)2 * n_nodes * D;
    const float* ef2  = e_feats + (size_t)2 * n_edges * DE;

    // sort work rides inside the rec launches on idle SMs (rec uses only 4):
    //   rec#1 extra CTAs: histogram, rec#2: scan, rec#3: scatter+edge dots.
    // launch order puts rec#2 at ncu index 5 (-s 5 -c 1).
    int hist_ctas = (n_edges + 1023) / 1024;              // 782
    int extra[3]  = { hist_ctas, 2, hist_ctas };          // even grid for cluster=2

    k_zero_cnt<<<(NN + 256) / 256, 256>>>();                          // 0
    k_transpose_wih<<<(2 * G4 * D + 255) / 256, 256>>>(Wih);          // 1
    for (int call = 0; call < 3; call++) {
        k_lstm_g0<<<dim3(D / 4, 2), 512>>>(W0, call > 0, bih, bhh);   // 2,4,6
        k_lstm_rec<<<4 + extra[call], 1024>>>(Whh, call, src2, dst2, ef2, a_w); // 3,5,7
    }

    for (int layer = 0; layer < 2; layer++) {
        k_gat_gemm<<<(n_nodes + 63) / 64, 256, smem_gemm>>>(nf2, layer, a_w);
        k_node_fused<<<(n_nodes * 32 + 255) / 256, 256>>>((float*)d_out, layer == 0 ? 1 : 0, layer);
    }
}